// round 16
// baseline (speedup 1.0000x reference)
#include <cuda_runtime.h>
#include <cuda_bf16.h>
#include <cuda_fp16.h>
#include <math.h>
#include <stdint.h>

#define NN 100000
#define NE 1600000
#define FIN 602
#define NH  128
#define NC  41
#define GP  42                     // g_g row pitch (floats), col 41 = zero pad

// ---------------- scratch (device globals: no runtime allocation allowed) ----
__device__ int   g_is64;
__device__ int   g_deg[NN];
__device__ int   g_incl[NN];
__device__ int   g_part[512];
__device__ int   g_off[NN];
__device__ int   g_cur[NN];
__device__ int   g_src[NE];
__device__ float g_dinv[NN];
__device__ __half g_dinvh[NN];
__device__ __half g_h2[(size_t)NN * NH];      // x @ W1 fp16; after k_hscale: dinv-prescaled
__device__ __half g_a2[(size_t)NN * NH];      // relu layer-1 output, fp16
__device__ float g_g[(size_t)NN * GP];        // dinv-prescaled logits, fp32, pitch 42
__device__ __nv_bfloat16 g_w1b[128 * 608];    // W1^T bf16, [n][k], K padded
__device__ __half g_w2h[64 * 128];            // W2^T fp16, [n][k], N padded to 64

// ---------------- helpers -----------------------------------------------------
__device__ __forceinline__ uint32_t smem_to_u32(const void* p) {
    uint32_t a;
    asm("{ .reg .u64 t; cvta.to.shared.u64 t, %1; cvt.u32.u64 %0, t; }" : "=r"(a) : "l"(p));
    return a;
}
__device__ __forceinline__ uint32_t pack_bf2(float a, float b) {
    __nv_bfloat162 v = __floats2bfloat162_rn(a, b);
    return *reinterpret_cast<uint32_t*>(&v);
}
__device__ __forceinline__ void mma16(float* d, const uint32_t* a, uint32_t b0, uint32_t b1) {
    asm volatile(
        "mma.sync.aligned.m16n8k16.row.col.f32.bf16.bf16.f32 "
        "{%0,%1,%2,%3}, {%4,%5,%6,%7}, {%8,%9}, {%0,%1,%2,%3};"
        : "+f"(d[0]), "+f"(d[1]), "+f"(d[2]), "+f"(d[3])
        : "r"(a[0]), "r"(a[1]), "r"(a[2]), "r"(a[3]), "r"(b0), "r"(b1));
}
__device__ __forceinline__ void mma16h(float* d, const uint32_t* a, uint32_t b0, uint32_t b1) {
    asm volatile(
        "mma.sync.aligned.m16n8k16.row.col.f32.f16.f16.f32 "
        "{%0,%1,%2,%3}, {%4,%5,%6,%7}, {%8,%9}, {%0,%1,%2,%3};"
        : "+f"(d[0]), "+f"(d[1]), "+f"(d[2]), "+f"(d[3])
        : "r"(a[0]), "r"(a[1]), "r"(a[2]), "r"(a[3]), "r"(b0), "r"(b1));
}
__device__ __forceinline__ void ldsm4(uint32_t& r0, uint32_t& r1, uint32_t& r2, uint32_t& r3,
                                      uint32_t addr) {
    asm volatile("ldmatrix.sync.aligned.m8n8.x4.shared.b16 {%0,%1,%2,%3}, [%4];"
                 : "=r"(r0), "=r"(r1), "=r"(r2), "=r"(r3) : "r"(addr));
}

// ---------------- edge index loader (dtype-agnostic) --------------------------
__device__ __forceinline__ int eidx(const void* e, long long i) {
    if (g_is64) return (int)((const long long*)e)[i];
    return ((const int*)e)[i];
}

// ---------------- setup kernels ------------------------------------------------
__global__ void k_init() {
    int i = blockIdx.x * blockDim.x + threadIdx.x;
    if (i < NN) { g_deg[i] = 0; g_cur[i] = 0; }
    if (i == 0) g_is64 = 1;
}

__global__ void k_detect(const unsigned* e32) {
    int t = threadIdx.x;
    if (e32[2 * t + 1] != 0u) atomicExch(&g_is64, 0);
}

__global__ void k_deg(const void* e) {
    int i = blockIdx.x * blockDim.x + threadIdx.x;
    if (i < NE) atomicAdd(&g_deg[eidx(e, (long long)NE + i)], 1);
}

// scan1 also computes dinv (g_deg is final here)
__global__ void k_scan1() {
    __shared__ int s[256];
    int b = blockIdx.x, t = threadIdx.x;
    int i = b * 256 + t;
    int v = (i < NN) ? g_deg[i] : 0;
    if (i < NN) {
        float d = rsqrtf((float)(v + 1));
        g_dinv[i] = d;
        g_dinvh[i] = __float2half(d);
    }
    s[t] = v; __syncthreads();
    for (int o = 1; o < 256; o <<= 1) {
        int x = (t >= o) ? s[t - o] : 0;
        __syncthreads(); s[t] += x; __syncthreads();
    }
    if (i < NN) g_incl[i] = s[t];
    if (t == 255) g_part[b] = s[255];
}

__global__ void k_scan2() {
    __shared__ int s[512];
    int t = threadIdx.x;
    const int NB = (NN + 255) / 256;
    int v = (t < NB) ? g_part[t] : 0;
    s[t] = v; __syncthreads();
    for (int o = 1; o < 512; o <<= 1) {
        int x = (t >= o) ? s[t - o] : 0;
        __syncthreads(); s[t] += x; __syncthreads();
    }
    if (t < NB) g_part[t] = s[t] - v;
}

__global__ void k_scan3() {
    int i = blockIdx.x * blockDim.x + threadIdx.x;
    if (i < NN) g_off[i] = g_part[i / 256] + g_incl[i] - g_deg[i];
}

__global__ void k_scatter(const void* e) {
    int i = blockIdx.x * blockDim.x + threadIdx.x;
    if (i < NE) {
        int s = eidx(e, i);
        int d = eidx(e, (long long)NE + i);
        g_src[g_off[d] + atomicAdd(&g_cur[d], 1)] = s;
    }
}

// ---------------- W1 transpose to bf16 ------------------------------------------
__global__ void k_w1split(const float* __restrict__ W1) {
    int i = blockIdx.x * blockDim.x + threadIdx.x;
    if (i >= 128 * 608) return;
    int n = i / 608, k = i % 608;
    float v = (k < FIN) ? W1[k * NH + n] : 0.f;
    g_w1b[i] = __float2bfloat16(v);
}

// ---------------- W2 transpose + pad to fp16 [64][128] --------------------------
__global__ void k_w2split(const float* __restrict__ W2) {
    int i = blockIdx.x * blockDim.x + threadIdx.x;
    if (i >= 64 * 128) return;
    int n = i / 128, k = i % 128;
    float v = (n < NC) ? W2[k * NC + n] : 0.f;
    g_w2h[i] = __float2half(v);
}

// ---------------- GEMM1: g_h2 = fp16(x @ W1) via mma.sync bf16 (single term) ----
#define STG  10240                 // one stage: 128 rows * 80 B
#define AH_O 0
#define BH_O (2 * STG)
#define SMEM_G1 (4 * STG)          // 40960 B

__global__ __launch_bounds__(256, 2) void k_gemm1_mma(const float* __restrict__ X) {
    extern __shared__ char smem[];
    const uint32_t sb = smem_to_u32(smem);
    const int t = threadIdx.x;
    const int lane = t & 31, w = t >> 5;
    const int wm = w >> 2, wn = w & 3;
    const int lq = lane >> 2, lr = lane & 3;
    const int m0 = blockIdx.x * 128;

    const int seg = lane >> 3, li = lane & 7;
    const uint32_t aRowB = (uint32_t)((wm * 64 + ((seg & 1) << 3) + li) * 80);
    const uint32_t aColH = (uint32_t)(((seg >> 1) << 3) * 2);
    const uint32_t bRowB = (uint32_t)((wn * 32 + ((seg >> 1) << 3) + li) * 80);
    const uint32_t bColH = (uint32_t)(((seg & 1) << 3) * 2);

    const int r0a = (t + 0)   >> 2, q0a = t & 3;
    const int r1a = (t + 256) >> 2, q1a = t & 3;

    float acc[4][4][4];
#pragma unroll
    for (int i = 0; i < 4; i++)
#pragma unroll
        for (int j = 0; j < 4; j++)
#pragma unroll
            for (int q = 0; q < 4; q++) acc[i][j][q] = 0.f;

    const int NIT = 19;
    float f[2][8];

    auto LDGA = [&](int it) {
        const int k0 = it * 32;
#pragma unroll
        for (int i = 0; i < 2; i++) {
            int row = i ? r1a : r0a;
            int q   = i ? q1a : q0a;
            int rg = m0 + row;
            int kc = k0 + q * 8;
            const float* p = X + (size_t)rg * FIN + kc;
#pragma unroll
            for (int j = 0; j < 4; j++) {
                int k = kc + 2 * j;
                float2 v = (rg < NN && k < FIN) ? *(const float2*)(p + 2 * j)
                                                : make_float2(0.f, 0.f);
                f[i][2 * j] = v.x; f[i][2 * j + 1] = v.y;
            }
        }
    };
    auto STSA = [&](int st) {
#pragma unroll
        for (int i = 0; i < 2; i++) {
            int row = i ? r1a : r0a;
            int q   = i ? q1a : q0a;
            uint32_t hp[4];
#pragma unroll
            for (int j = 0; j < 4; j++)
                hp[j] = pack_bf2(f[i][2 * j], f[i][2 * j + 1]);
            uint32_t off = (uint32_t)(st * STG + row * 80 + q * 16);
            *reinterpret_cast<uint4*>(smem + AH_O + off) = make_uint4(hp[0], hp[1], hp[2], hp[3]);
        }
    };
    auto CPB = [&](int it, int st) {
        const int k0 = it * 32;
#pragma unroll
        for (int i = 0; i < 2; i++) {
            int row = i ? r1a : r0a;
            int q   = i ? q1a : q0a;
            uint32_t off = (uint32_t)(st * STG + row * 80 + q * 16);
            const __nv_bfloat16* sh = g_w1b + row * 608 + k0 + q * 8;
            asm volatile("cp.async.cg.shared.global [%0], [%1], 16;"
                         :: "r"(sb + BH_O + off), "l"(sh));
        }
    };

    LDGA(0); STSA(0); CPB(0, 0);
    asm volatile("cp.async.commit_group;");

    for (int it = 0; it < NIT; it++) {
        const int cur = it & 1;
        if (it + 1 < NIT) {
            LDGA(it + 1);
            CPB(it + 1, cur ^ 1);
            asm volatile("cp.async.commit_group;");
            asm volatile("cp.async.wait_group 1;");
        } else {
            asm volatile("cp.async.wait_group 0;");
        }
        __syncthreads();

        const uint32_t stgO = (uint32_t)(cur * STG);
#pragma unroll
        for (int step = 0; step < 2; step++) {
            const uint32_t scol = (uint32_t)(step * 32);
            uint32_t bh[2][4];
#pragma unroll
            for (int p = 0; p < 2; p++) {
                uint32_t off = stgO + bRowB + (uint32_t)(p * 16 * 80) + scol + bColH;
                ldsm4(bh[p][0], bh[p][1], bh[p][2], bh[p][3], sb + BH_O + off);
            }
#pragma unroll
            for (int mt = 0; mt < 4; mt++) {
                uint32_t off = stgO + aRowB + (uint32_t)(mt * 16 * 80) + scol + aColH;
                uint32_t ah[4];
                ldsm4(ah[0], ah[1], ah[2], ah[3], sb + AH_O + off);
#pragma unroll
                for (int nt = 0; nt < 4; nt++) {
                    const int p = nt >> 1, hx = (nt & 1) * 2;
                    mma16(acc[mt][nt], ah, bh[p][hx], bh[p][hx + 1]);
                }
            }
        }
        if (it + 1 < NIT) STSA(cur ^ 1);
        __syncthreads();
    }

    // epilogue: fp16 output
#pragma unroll
    for (int mt = 0; mt < 4; mt++) {
        int r0 = m0 + wm * 64 + mt * 16 + lq;
        int r1 = r0 + 8;
#pragma unroll
        for (int nt = 0; nt < 4; nt++) {
            int c = wn * 32 + nt * 8 + 2 * lr;
            if (r0 < NN)
                *(__half2*)&g_h2[(size_t)r0 * NH + c] =
                    __floats2half2_rn(acc[mt][nt][0], acc[mt][nt][1]);
            if (r1 < NN)
                *(__half2*)&g_h2[(size_t)r1 * NH + c] =
                    __floats2half2_rn(acc[mt][nt][2], acc[mt][nt][3]);
        }
    }
}

// ---------------- hscale: g_h2[row] *= dinv[row]  (runs at the join) ------------
__global__ void k_hscale() {
    int i = blockIdx.x * blockDim.x + threadIdx.x;   // one uint4 = 8 halfs
    if (i >= NN * (NH / 8)) return;
    int row = i >> 4;                                 // 16 chunks per row
    __half2 d = __half2half2(g_dinvh[row]);
    uint4 v = *((const uint4*)g_h2 + i);
    __half2* p = reinterpret_cast<__half2*>(&v);
    p[0] = __hmul2(p[0], d);
    p[1] = __hmul2(p[1], d);
    p[2] = __hmul2(p[2], d);
    p[3] = __hmul2(p[3], d);
    *((uint4*)g_h2 + i) = v;
}

// ---------------- Aggregation layer 1: warp/node, HADD2 on prescaled rows -------
__global__ void k_agg1(const float* __restrict__ b1) {
    int w = (blockIdx.x * blockDim.x + threadIdx.x) >> 5;
    int lane = threadIdx.x & 31;
    if (w >= NN) return;
    __half2 a0 = __floats2half2_rn(0.f, 0.f);
    __half2 a1 = a0;
    int beg = g_off[w], end = beg + g_deg[w];
    int e = beg;
    const int co = lane * 4;
    for (; e + 4 <= end; e += 4) {
        int s0 = g_src[e], s1 = g_src[e + 1], s2 = g_src[e + 2], s3 = g_src[e + 3];
        uint2 r0 = *(const uint2*)(g_h2 + (size_t)s0 * NH + co);
        uint2 r1 = *(const uint2*)(g_h2 + (size_t)s1 * NH + co);
        uint2 r2 = *(const uint2*)(g_h2 + (size_t)s2 * NH + co);
        uint2 r3 = *(const uint2*)(g_h2 + (size_t)s3 * NH + co);
        a0 = __hadd2(a0, *reinterpret_cast<__half2*>(&r0.x));
        a1 = __hadd2(a1, *reinterpret_cast<__half2*>(&r0.y));
        a0 = __hadd2(a0, *reinterpret_cast<__half2*>(&r1.x));
        a1 = __hadd2(a1, *reinterpret_cast<__half2*>(&r1.y));
        a0 = __hadd2(a0, *reinterpret_cast<__half2*>(&r2.x));
        a1 = __hadd2(a1, *reinterpret_cast<__half2*>(&r2.y));
        a0 = __hadd2(a0, *reinterpret_cast<__half2*>(&r3.x));
        a1 = __hadd2(a1, *reinterpret_cast<__half2*>(&r3.y));
    }
    for (; e < end; e++) {
        int s = g_src[e];
        uint2 r = *(const uint2*)(g_h2 + (size_t)s * NH + co);
        a0 = __hadd2(a0, *reinterpret_cast<__half2*>(&r.x));
        a1 = __hadd2(a1, *reinterpret_cast<__half2*>(&r.y));
    }
    {
        uint2 r = *(const uint2*)(g_h2 + (size_t)w * NH + co);   // self: already dinv-scaled
        a0 = __hadd2(a0, *reinterpret_cast<__half2*>(&r.x));
        a1 = __hadd2(a1, *reinterpret_cast<__half2*>(&r.y));
    }
    float dd = g_dinv[w];
    float2 f0 = __half22float2(a0);
    float2 f1 = __half22float2(a1);
    float4 bv = *(const float4*)(b1 + co);
    __half2 o0 = __floats2half2_rn(fmaxf(fmaf(dd, f0.x, bv.x), 0.f),
                                   fmaxf(fmaf(dd, f0.y, bv.y), 0.f));
    __half2 o1 = __floats2half2_rn(fmaxf(fmaf(dd, f1.x, bv.z), 0.f),
                                   fmaxf(fmaf(dd, f1.y, bv.w), 0.f));
    uint2 packed;
    packed.x = *reinterpret_cast<uint32_t*>(&o0);
    packed.y = *reinterpret_cast<uint32_t*>(&o1);
    *(uint2*)(g_a2 + (size_t)w * NH + co) = packed;
}

// ---------------- GEMM2 via mma: g_g = dinv * (g_a2 @ W2), fp16 inputs -----------
#define G2P   272
#define G2A_O 0
#define G2B_O (128 * G2P)
#define SMEM_G2 (128 * G2P + 64 * G2P)   // 52224 B

__global__ __launch_bounds__(256, 2) void k_gemm2_mma() {
    extern __shared__ char smem[];
    const uint32_t sb = smem_to_u32(smem);
    const int t = threadIdx.x;
    const int lane = t & 31, w = t >> 5;
    const int wm = w >> 2, wn = w & 3;
    const int lq = lane >> 2, lr = lane & 3;
    const int m0 = blockIdx.x * 128;

    const int seg = lane >> 3, li = lane & 7;
    const uint32_t aRowB = (uint32_t)((wm * 64 + ((seg & 1) << 3) + li) * G2P);
    const uint32_t aColH = (uint32_t)(((seg >> 1) << 3) * 2);
    const uint32_t bRowB = (uint32_t)((wn * 16 + ((seg >> 1) << 3) + li) * G2P);
    const uint32_t bColH = (uint32_t)(((seg & 1) << 3) * 2);

#pragma unroll
    for (int i = 0; i < 8; i++) {
        int id = t + i * 256;
        int row = id >> 4, cq = id & 15;
        uint32_t dst = sb + G2A_O + (uint32_t)(row * G2P + cq * 16);
        const __half* src = g_a2 + (size_t)(m0 + row) * NH + cq * 8;
        int sz = (m0 + row < NN) ? 16 : 0;
        if (!sz) src = g_a2;
        asm volatile("cp.async.cg.shared.global [%0], [%1], 16, %2;"
                     :: "r"(dst), "l"(src), "r"(sz));
    }
#pragma unroll
    for (int i = 0; i < 4; i++) {
        int id = t + i * 256;
        int row = id >> 4, cq = id & 15;
        uint32_t dst = sb + G2B_O + (uint32_t)(row * G2P + cq * 16);
        const __half* src = g_w2h + row * 128 + cq * 8;
        asm volatile("cp.async.cg.shared.global [%0], [%1], 16;" :: "r"(dst), "l"(src));
    }
    asm volatile("cp.async.commit_group;");
    asm volatile("cp.async.wait_group 0;");
    __syncthreads();

    float acc[4][2][4];
#pragma unroll
    for (int i = 0; i < 4; i++)
#pragma unroll
        for (int j = 0; j < 2; j++)
#pragma unroll
            for (int q = 0; q < 4; q++) acc[i][j][q] = 0.f;

#pragma unroll
    for (int step = 0; step < 8; step++) {
        const uint32_t scol = (uint32_t)(step * 32);
        uint32_t bh[4];
        ldsm4(bh[0], bh[1], bh[2], bh[3], sb + G2B_O + bRowB + scol + bColH);
#pragma unroll
        for (int mt = 0; mt < 4; mt++) {
            uint32_t ah[4];
            ldsm4(ah[0], ah[1], ah[2], ah[3],
                  sb + G2A_O + aRowB + (uint32_t)(mt * 16 * G2P) + scol + aColH);
            mma16h(acc[mt][0], ah, bh[0], bh[1]);
            mma16h(acc[mt][1], ah, bh[2], bh[3]);
        }
    }

    // epilogue: dinv-prescale, write cols < GP (col 41 is zero pad from W2)
#pragma unroll
    for (int mt = 0; mt < 4; mt++) {
        int r0 = m0 + wm * 64 + mt * 16 + lq;
        int r1 = r0 + 8;
        float d0 = (r0 < NN) ? g_dinv[r0] : 0.f;
        float d1 = (r1 < NN) ? g_dinv[r1] : 0.f;
#pragma unroll
        for (int nt = 0; nt < 2; nt++) {
            int c = wn * 16 + nt * 8 + 2 * lr;
            if (r0 < NN) {
                if (c < GP)     g_g[(size_t)r0 * GP + c]     = d0 * acc[mt][nt][0];
                if (c + 1 < GP) g_g[(size_t)r0 * GP + c + 1] = d0 * acc[mt][nt][1];
            }
            if (r1 < NN) {
                if (c < GP)     g_g[(size_t)r1 * GP + c]     = d1 * acc[mt][nt][2];
                if (c + 1 < GP) g_g[(size_t)r1 * GP + c + 1] = d1 * acc[mt][nt][3];
            }
        }
    }
}

// ---------------- Aggregation layer 2 + bias + log_softmax (paired cols) --------
__global__ void k_agg2(const float* __restrict__ b2, float* __restrict__ out) {
    int w = (blockIdx.x * blockDim.x + threadIdx.x) >> 5;
    int lane = threadIdx.x & 31;
    if (w >= NN) return;
    float a0 = 0.f, a1 = 0.f;
    const int c = 2 * lane;
    const bool act = c < GP;
    int beg = g_off[w], end = beg + g_deg[w];
    if (act) {
        int e = beg;
        for (; e + 4 <= end; e += 4) {
            int s0 = g_src[e], s1 = g_src[e + 1], s2 = g_src[e + 2], s3 = g_src[e + 3];
            float2 v0 = *(const float2*)(g_g + (size_t)s0 * GP + c);
            float2 v1 = *(const float2*)(g_g + (size_t)s1 * GP + c);
            float2 v2 = *(const float2*)(g_g + (size_t)s2 * GP + c);
            float2 v3 = *(const float2*)(g_g + (size_t)s3 * GP + c);
            a0 += v0.x + v1.x + v2.x + v3.x;
            a1 += v0.y + v1.y + v2.y + v3.y;
        }
        for (; e < end; e++) {
            float2 v = *(const float2*)(g_g + (size_t)g_src[e] * GP + c);
            a0 += v.x; a1 += v.y;
        }
        float2 v = *(const float2*)(g_g + (size_t)w * GP + c);
        a0 += v.x; a1 += v.y;
    }

    float dd = g_dinv[w];
    float v0 = (c < NC)     ? (dd * a0 + b2[c])     : -INFINITY;
    float v1 = (c + 1 < NC) ? (dd * a1 + b2[c + 1]) : -INFINITY;

    float m = fmaxf(v0, v1);
#pragma unroll
    for (int o = 16; o; o >>= 1) m = fmaxf(m, __shfl_xor_sync(0xffffffffu, m, o));
    float s = ((c < NC) ? expf(v0 - m) : 0.f) + ((c + 1 < NC) ? expf(v1 - m) : 0.f);
#pragma unroll
    for (int o = 16; o; o >>= 1) s += __shfl_xor_sync(0xffffffffu, s, o);
    float ls = logf(s) + m;

    if (c < NC)     out[(size_t)w * NC + c]     = v0 - ls;
    if (c + 1 < NC) out[(size_t)w * NC + c + 1] = v1 - ls;
}

// ---------------- launch -----------------------------------------------------------
extern "C" void kernel_launch(void* const* d_in, const int* in_sizes, int n_in,
                              void* d_out, int out_size) {
    const float* x  = (const float*)d_in[0];
    const void*  e  = d_in[1];
    const float* W1 = (const float*)d_in[2];
    const float* b1 = (const float*)d_in[3];
    const float* W2 = (const float*)d_in[4];
    const float* b2 = (const float*)d_in[5];
    float* out = (float*)d_out;

    cudaFuncSetAttribute(k_gemm1_mma, cudaFuncAttributeMaxDynamicSharedMemorySize, SMEM_G1);
    cudaFuncSetAttribute(k_gemm2_mma, cudaFuncAttributeMaxDynamicSharedMemorySize, SMEM_G2);

    cudaStream_t s;
    cudaEvent_t evFork, evJoin;
    cudaStreamCreateWithFlags(&s, cudaStreamNonBlocking);
    cudaEventCreateWithFlags(&evFork, cudaEventDisableTiming);
    cudaEventCreateWithFlags(&evJoin, cudaEventDisableTiming);

    cudaEventRecord(evFork, 0);
    cudaStreamWaitEvent(s, evFork, 0);

    // GEMM branch (side stream)
    k_w1split<<<(128 * 608 + 255) / 256, 256, 0, s>>>(W1);
    k_gemm1_mma<<<(NN + 127) / 128, 256, SMEM_G1, s>>>(x);
    cudaEventRecord(evJoin, s);

    // prep branch (main/capture stream)
    k_init<<<(NN + 255) / 256, 256>>>();
    k_detect<<<1, 256>>>((const unsigned*)e);
    k_deg<<<(NE + 255) / 256, 256>>>(e);
    k_scan1<<<(NN + 255) / 256, 256>>>();
    k_scan2<<<1, 512>>>();
    k_scan3<<<(NN + 255) / 256, 256>>>();
    k_scatter<<<(NE + 255) / 256, 256>>>(e);
    k_w2split<<<(64 * 128 + 255) / 256, 256>>>(W2);

    cudaStreamWaitEvent(0, evJoin, 0);

    k_hscale<<<(NN * (NH / 8) + 255) / 256, 256>>>();
    k_agg1<<<(NN * 32 + 255) / 256, 256>>>(b1);
    k_gemm2_mma<<<(NN + 127) / 128, 256, SMEM_G2>>>();
    k_agg2<<<(NN * 32 + 255) / 256, 256>>>(b2, out);
}

// round 17
// speedup vs baseline: 1.0277x; 1.0277x over previous
#include <cuda_runtime.h>
#include <cuda_bf16.h>
#include <cuda_fp16.h>
#include <math.h>
#include <stdint.h>

#define NN 100000
#define NE 1600000
#define FIN 602
#define NH  128
#define NC  41
#define GP  44                     // g_g2 row pitch (halfs); cols 41..43 zero pad

// ---------------- scratch (device globals: no runtime allocation allowed) ----
__device__ int   g_is64;
__device__ int   g_deg[NN];
__device__ int   g_incl[NN];
__device__ int   g_part[512];
__device__ int   g_off[NN];
__device__ int   g_cur[NN];
__device__ int   g_src[NE];
__device__ float g_dinv[NN];
__device__ __half g_dinvh[NN];
__device__ __half g_h2[(size_t)NN * NH];      // x @ W1 in fp16 (agg1 gather table)
__device__ __half g_a2[(size_t)NN * NH];      // relu layer-1 output, fp16
__device__ __half g_g2[(size_t)NN * GP];      // dinv-prescaled logits, fp16, pitch 44
__device__ __nv_bfloat16 g_w1b[128 * 608];    // W1^T bf16, [n][k], K padded
__device__ __half g_w2h[64 * 128];            // W2^T fp16, [n][k], N padded to 64

// ---------------- helpers -----------------------------------------------------
__device__ __forceinline__ uint32_t smem_to_u32(const void* p) {
    uint32_t a;
    asm("{ .reg .u64 t; cvta.to.shared.u64 t, %1; cvt.u32.u64 %0, t; }" : "=r"(a) : "l"(p));
    return a;
}
__device__ __forceinline__ uint32_t pack_bf2(float a, float b) {
    __nv_bfloat162 v = __floats2bfloat162_rn(a, b);
    return *reinterpret_cast<uint32_t*>(&v);
}
__device__ __forceinline__ void mma16(float* d, const uint32_t* a, uint32_t b0, uint32_t b1) {
    asm volatile(
        "mma.sync.aligned.m16n8k16.row.col.f32.bf16.bf16.f32 "
        "{%0,%1,%2,%3}, {%4,%5,%6,%7}, {%8,%9}, {%0,%1,%2,%3};"
        : "+f"(d[0]), "+f"(d[1]), "+f"(d[2]), "+f"(d[3])
        : "r"(a[0]), "r"(a[1]), "r"(a[2]), "r"(a[3]), "r"(b0), "r"(b1));
}
__device__ __forceinline__ void mma16h(float* d, const uint32_t* a, uint32_t b0, uint32_t b1) {
    asm volatile(
        "mma.sync.aligned.m16n8k16.row.col.f32.f16.f16.f32 "
        "{%0,%1,%2,%3}, {%4,%5,%6,%7}, {%8,%9}, {%0,%1,%2,%3};"
        : "+f"(d[0]), "+f"(d[1]), "+f"(d[2]), "+f"(d[3])
        : "r"(a[0]), "r"(a[1]), "r"(a[2]), "r"(a[3]), "r"(b0), "r"(b1));
}
__device__ __forceinline__ void ldsm4(uint32_t& r0, uint32_t& r1, uint32_t& r2, uint32_t& r3,
                                      uint32_t addr) {
    asm volatile("ldmatrix.sync.aligned.m8n8.x4.shared.b16 {%0,%1,%2,%3}, [%4];"
                 : "=r"(r0), "=r"(r1), "=r"(r2), "=r"(r3) : "r"(addr));
}

// ---------------- edge index loader (dtype-agnostic) --------------------------
__device__ __forceinline__ int eidx(const void* e, long long i) {
    if (g_is64) return (int)((const long long*)e)[i];
    return ((const int*)e)[i];
}

// ---------------- setup kernels ------------------------------------------------
__global__ void k_init() {
    int i = blockIdx.x * blockDim.x + threadIdx.x;
    if (i < NN) { g_deg[i] = 0; g_cur[i] = 0; }
    if (i == 0) g_is64 = 1;
}

__global__ void k_detect(const unsigned* e32) {
    int t = threadIdx.x;
    if (e32[2 * t + 1] != 0u) atomicExch(&g_is64, 0);
}

__global__ void k_deg(const void* e) {
    int i = blockIdx.x * blockDim.x + threadIdx.x;
    if (i < NE) atomicAdd(&g_deg[eidx(e, (long long)NE + i)], 1);
}

// scan1 also computes dinv (g_deg is final here)
__global__ void k_scan1() {
    __shared__ int s[256];
    int b = blockIdx.x, t = threadIdx.x;
    int i = b * 256 + t;
    int v = (i < NN) ? g_deg[i] : 0;
    if (i < NN) {
        float d = rsqrtf((float)(v + 1));
        g_dinv[i] = d;
        g_dinvh[i] = __float2half(d);
    }
    s[t] = v; __syncthreads();
    for (int o = 1; o < 256; o <<= 1) {
        int x = (t >= o) ? s[t - o] : 0;
        __syncthreads(); s[t] += x; __syncthreads();
    }
    if (i < NN) g_incl[i] = s[t];
    if (t == 255) g_part[b] = s[255];
}

__global__ void k_scan2() {
    __shared__ int s[512];
    int t = threadIdx.x;
    const int NB = (NN + 255) / 256;
    int v = (t < NB) ? g_part[t] : 0;
    s[t] = v; __syncthreads();
    for (int o = 1; o < 512; o <<= 1) {
        int x = (t >= o) ? s[t - o] : 0;
        __syncthreads(); s[t] += x; __syncthreads();
    }
    if (t < NB) g_part[t] = s[t] - v;
}

__global__ void k_scan3() {
    int i = blockIdx.x * blockDim.x + threadIdx.x;
    if (i < NN) g_off[i] = g_part[i / 256] + g_incl[i] - g_deg[i];
}

__global__ void k_scatter(const void* e) {
    int i = blockIdx.x * blockDim.x + threadIdx.x;
    if (i < NE) {
        int s = eidx(e, i);
        int d = eidx(e, (long long)NE + i);
        g_src[g_off[d] + atomicAdd(&g_cur[d], 1)] = s;
    }
}

// ---------------- W1 transpose to bf16 ------------------------------------------
__global__ void k_w1split(const float* __restrict__ W1) {
    int i = blockIdx.x * blockDim.x + threadIdx.x;
    if (i >= 128 * 608) return;
    int n = i / 608, k = i % 608;
    float v = (k < FIN) ? W1[k * NH + n] : 0.f;
    g_w1b[i] = __float2bfloat16(v);
}

// ---------------- W2 transpose + pad to fp16 [64][128] --------------------------
__global__ void k_w2split(const float* __restrict__ W2) {
    int i = blockIdx.x * blockDim.x + threadIdx.x;
    if (i >= 64 * 128) return;
    int n = i / 128, k = i % 128;
    float v = (n < NC) ? W2[k * NC + n] : 0.f;
    g_w2h[i] = __float2half(v);
}

// ---------------- GEMM1: g_h2 = fp16(x @ W1) via mma.sync bf16 (single term) ----
#define STG  10240                 // one stage: 128 rows * 80 B
#define AH_O 0
#define BH_O (2 * STG)
#define SMEM_G1 (4 * STG)          // 40960 B

__global__ __launch_bounds__(256, 2) void k_gemm1_mma(const float* __restrict__ X) {
    extern __shared__ char smem[];
    const uint32_t sb = smem_to_u32(smem);
    const int t = threadIdx.x;
    const int lane = t & 31, w = t >> 5;
    const int wm = w >> 2, wn = w & 3;
    const int lq = lane >> 2, lr = lane & 3;
    const int m0 = blockIdx.x * 128;

    const int seg = lane >> 3, li = lane & 7;
    const uint32_t aRowB = (uint32_t)((wm * 64 + ((seg & 1) << 3) + li) * 80);
    const uint32_t aColH = (uint32_t)(((seg >> 1) << 3) * 2);
    const uint32_t bRowB = (uint32_t)((wn * 32 + ((seg >> 1) << 3) + li) * 80);
    const uint32_t bColH = (uint32_t)(((seg & 1) << 3) * 2);

    const int r0a = (t + 0)   >> 2, q0a = t & 3;
    const int r1a = (t + 256) >> 2, q1a = t & 3;

    float acc[4][4][4];
#pragma unroll
    for (int i = 0; i < 4; i++)
#pragma unroll
        for (int j = 0; j < 4; j++)
#pragma unroll
            for (int q = 0; q < 4; q++) acc[i][j][q] = 0.f;

    const int NIT = 19;
    float f[2][8];

    auto LDGA = [&](int it) {
        const int k0 = it * 32;
#pragma unroll
        for (int i = 0; i < 2; i++) {
            int row = i ? r1a : r0a;
            int q   = i ? q1a : q0a;
            int rg = m0 + row;
            int kc = k0 + q * 8;
            const float* p = X + (size_t)rg * FIN + kc;
#pragma unroll
            for (int j = 0; j < 4; j++) {
                int k = kc + 2 * j;
                float2 v = (rg < NN && k < FIN) ? *(const float2*)(p + 2 * j)
                                                : make_float2(0.f, 0.f);
                f[i][2 * j] = v.x; f[i][2 * j + 1] = v.y;
            }
        }
    };
    auto STSA = [&](int st) {
#pragma unroll
        for (int i = 0; i < 2; i++) {
            int row = i ? r1a : r0a;
            int q   = i ? q1a : q0a;
            uint32_t hp[4];
#pragma unroll
            for (int j = 0; j < 4; j++)
                hp[j] = pack_bf2(f[i][2 * j], f[i][2 * j + 1]);
            uint32_t off = (uint32_t)(st * STG + row * 80 + q * 16);
            *reinterpret_cast<uint4*>(smem + AH_O + off) = make_uint4(hp[0], hp[1], hp[2], hp[3]);
        }
    };
    auto CPB = [&](int it, int st) {
        const int k0 = it * 32;
#pragma unroll
        for (int i = 0; i < 2; i++) {
            int row = i ? r1a : r0a;
            int q   = i ? q1a : q0a;
            uint32_t off = (uint32_t)(st * STG + row * 80 + q * 16);
            const __nv_bfloat16* sh = g_w1b + row * 608 + k0 + q * 8;
            asm volatile("cp.async.cg.shared.global [%0], [%1], 16;"
                         :: "r"(sb + BH_O + off), "l"(sh));
        }
    };

    LDGA(0); STSA(0); CPB(0, 0);
    asm volatile("cp.async.commit_group;");

    for (int it = 0; it < NIT; it++) {
        const int cur = it & 1;
        if (it + 1 < NIT) {
            LDGA(it + 1);
            CPB(it + 1, cur ^ 1);
            asm volatile("cp.async.commit_group;");
            asm volatile("cp.async.wait_group 1;");
        } else {
            asm volatile("cp.async.wait_group 0;");
        }
        __syncthreads();

        const uint32_t stgO = (uint32_t)(cur * STG);
#pragma unroll
        for (int step = 0; step < 2; step++) {
            const uint32_t scol = (uint32_t)(step * 32);
            uint32_t bh[2][4];
#pragma unroll
            for (int p = 0; p < 2; p++) {
                uint32_t off = stgO + bRowB + (uint32_t)(p * 16 * 80) + scol + bColH;
                ldsm4(bh[p][0], bh[p][1], bh[p][2], bh[p][3], sb + BH_O + off);
            }
#pragma unroll
            for (int mt = 0; mt < 4; mt++) {
                uint32_t off = stgO + aRowB + (uint32_t)(mt * 16 * 80) + scol + aColH;
                uint32_t ah[4];
                ldsm4(ah[0], ah[1], ah[2], ah[3], sb + AH_O + off);
#pragma unroll
                for (int nt = 0; nt < 4; nt++) {
                    const int p = nt >> 1, hx = (nt & 1) * 2;
                    mma16(acc[mt][nt], ah, bh[p][hx], bh[p][hx + 1]);
                }
            }
        }
        if (it + 1 < NIT) STSA(cur ^ 1);
        __syncthreads();
    }

    // epilogue: fp16 output
#pragma unroll
    for (int mt = 0; mt < 4; mt++) {
        int r0 = m0 + wm * 64 + mt * 16 + lq;
        int r1 = r0 + 8;
#pragma unroll
        for (int nt = 0; nt < 4; nt++) {
            int c = wn * 32 + nt * 8 + 2 * lr;
            if (r0 < NN)
                *(__half2*)&g_h2[(size_t)r0 * NH + c] =
                    __floats2half2_rn(acc[mt][nt][0], acc[mt][nt][1]);
            if (r1 < NN)
                *(__half2*)&g_h2[(size_t)r1 * NH + c] =
                    __floats2half2_rn(acc[mt][nt][2], acc[mt][nt][3]);
        }
    }
}

// ---------------- Aggregation layer 1: warp/node, half2 accumulation ------------
__global__ void k_agg1(const float* __restrict__ b1) {
    int w = (blockIdx.x * blockDim.x + threadIdx.x) >> 5;
    int lane = threadIdx.x & 31;
    if (w >= NN) return;
    __half2 a0 = __floats2half2_rn(0.f, 0.f);
    __half2 a1 = a0;
    int beg = g_off[w], end = beg + g_deg[w];
    int e = beg;
    const int co = lane * 4;
    for (; e + 4 <= end; e += 4) {
        int s0 = g_src[e], s1 = g_src[e + 1], s2 = g_src[e + 2], s3 = g_src[e + 3];
        __half2 w0 = __half2half2(g_dinvh[s0]);
        __half2 w1 = __half2half2(g_dinvh[s1]);
        __half2 w2 = __half2half2(g_dinvh[s2]);
        __half2 w3 = __half2half2(g_dinvh[s3]);
        uint2 r0 = *(const uint2*)(g_h2 + (size_t)s0 * NH + co);
        uint2 r1 = *(const uint2*)(g_h2 + (size_t)s1 * NH + co);
        uint2 r2 = *(const uint2*)(g_h2 + (size_t)s2 * NH + co);
        uint2 r3 = *(const uint2*)(g_h2 + (size_t)s3 * NH + co);
        a0 = __hfma2(*reinterpret_cast<__half2*>(&r0.x), w0, a0);
        a1 = __hfma2(*reinterpret_cast<__half2*>(&r0.y), w0, a1);
        a0 = __hfma2(*reinterpret_cast<__half2*>(&r1.x), w1, a0);
        a1 = __hfma2(*reinterpret_cast<__half2*>(&r1.y), w1, a1);
        a0 = __hfma2(*reinterpret_cast<__half2*>(&r2.x), w2, a0);
        a1 = __hfma2(*reinterpret_cast<__half2*>(&r2.y), w2, a1);
        a0 = __hfma2(*reinterpret_cast<__half2*>(&r3.x), w3, a0);
        a1 = __hfma2(*reinterpret_cast<__half2*>(&r3.y), w3, a1);
    }
    for (; e < end; e++) {
        int s = g_src[e];
        __half2 ws = __half2half2(g_dinvh[s]);
        uint2 r = *(const uint2*)(g_h2 + (size_t)s * NH + co);
        a0 = __hfma2(*reinterpret_cast<__half2*>(&r.x), ws, a0);
        a1 = __hfma2(*reinterpret_cast<__half2*>(&r.y), ws, a1);
    }
    {
        __half2 ws = __half2half2(g_dinvh[w]);
        uint2 r = *(const uint2*)(g_h2 + (size_t)w * NH + co);
        a0 = __hfma2(*reinterpret_cast<__half2*>(&r.x), ws, a0);
        a1 = __hfma2(*reinterpret_cast<__half2*>(&r.y), ws, a1);
    }
    float dd = g_dinv[w];
    float2 f0 = __half22float2(a0);
    float2 f1 = __half22float2(a1);
    float4 bv = *(const float4*)(b1 + co);
    __half2 o0 = __floats2half2_rn(fmaxf(fmaf(dd, f0.x, bv.x), 0.f),
                                   fmaxf(fmaf(dd, f0.y, bv.y), 0.f));
    __half2 o1 = __floats2half2_rn(fmaxf(fmaf(dd, f1.x, bv.z), 0.f),
                                   fmaxf(fmaf(dd, f1.y, bv.w), 0.f));
    uint2 packed;
    packed.x = *reinterpret_cast<uint32_t*>(&o0);
    packed.y = *reinterpret_cast<uint32_t*>(&o1);
    *(uint2*)(g_a2 + (size_t)w * NH + co) = packed;
}

// ---------------- GEMM2 via mma: g_g2 = fp16(dinv * (g_a2 @ W2)) -----------------
#define G2P   272
#define G2A_O 0
#define G2B_O (128 * G2P)
#define SMEM_G2 (128 * G2P + 64 * G2P)   // 52224 B

__global__ __launch_bounds__(256, 2) void k_gemm2_mma() {
    extern __shared__ char smem[];
    const uint32_t sb = smem_to_u32(smem);
    const int t = threadIdx.x;
    const int lane = t & 31, w = t >> 5;
    const int wm = w >> 2, wn = w & 3;
    const int lq = lane >> 2, lr = lane & 3;
    const int m0 = blockIdx.x * 128;

    const int seg = lane >> 3, li = lane & 7;
    const uint32_t aRowB = (uint32_t)((wm * 64 + ((seg & 1) << 3) + li) * G2P);
    const uint32_t aColH = (uint32_t)(((seg >> 1) << 3) * 2);
    const uint32_t bRowB = (uint32_t)((wn * 16 + ((seg >> 1) << 3) + li) * G2P);
    const uint32_t bColH = (uint32_t)(((seg & 1) << 3) * 2);

#pragma unroll
    for (int i = 0; i < 8; i++) {
        int id = t + i * 256;
        int row = id >> 4, cq = id & 15;
        uint32_t dst = sb + G2A_O + (uint32_t)(row * G2P + cq * 16);
        const __half* src = g_a2 + (size_t)(m0 + row) * NH + cq * 8;
        int sz = (m0 + row < NN) ? 16 : 0;
        if (!sz) src = g_a2;
        asm volatile("cp.async.cg.shared.global [%0], [%1], 16, %2;"
                     :: "r"(dst), "l"(src), "r"(sz));
    }
#pragma unroll
    for (int i = 0; i < 4; i++) {
        int id = t + i * 256;
        int row = id >> 4, cq = id & 15;
        uint32_t dst = sb + G2B_O + (uint32_t)(row * G2P + cq * 16);
        const __half* src = g_w2h + row * 128 + cq * 8;
        asm volatile("cp.async.cg.shared.global [%0], [%1], 16;" :: "r"(dst), "l"(src));
    }
    asm volatile("cp.async.commit_group;");
    asm volatile("cp.async.wait_group 0;");
    __syncthreads();

    float acc[4][2][4];
#pragma unroll
    for (int i = 0; i < 4; i++)
#pragma unroll
        for (int j = 0; j < 2; j++)
#pragma unroll
            for (int q = 0; q < 4; q++) acc[i][j][q] = 0.f;

#pragma unroll
    for (int step = 0; step < 8; step++) {
        const uint32_t scol = (uint32_t)(step * 32);
        uint32_t bh[4];
        ldsm4(bh[0], bh[1], bh[2], bh[3], sb + G2B_O + bRowB + scol + bColH);
#pragma unroll
        for (int mt = 0; mt < 4; mt++) {
            uint32_t ah[4];
            ldsm4(ah[0], ah[1], ah[2], ah[3],
                  sb + G2A_O + aRowB + (uint32_t)(mt * 16 * G2P) + scol + aColH);
            mma16h(acc[mt][0], ah, bh[0], bh[1]);
            mma16h(acc[mt][1], ah, bh[2], bh[3]);
        }
    }

    // epilogue: dinv-prescale, fp16 pair stores, cols < GP (cols 41..43 zero pad)
#pragma unroll
    for (int mt = 0; mt < 4; mt++) {
        int r0 = m0 + wm * 64 + mt * 16 + lq;
        int r1 = r0 + 8;
        float d0 = (r0 < NN) ? g_dinv[r0] : 0.f;
        float d1 = (r1 < NN) ? g_dinv[r1] : 0.f;
#pragma unroll
        for (int nt = 0; nt < 2; nt++) {
            int c = wn * 16 + nt * 8 + 2 * lr;
            if (c < GP) {
                if (r0 < NN)
                    *(__half2*)&g_g2[(size_t)r0 * GP + c] =
                        __floats2half2_rn(d0 * acc[mt][nt][0], d0 * acc[mt][nt][1]);
                if (r1 < NN)
                    *(__half2*)&g_g2[(size_t)r1 * GP + c] =
                        __floats2half2_rn(d1 * acc[mt][nt][2], d1 * acc[mt][nt][3]);
            }
        }
    }
}

// ---------------- Aggregation layer 2 + bias + log_softmax (fp16 paired cols) ---
__global__ void k_agg2(const float* __restrict__ b2, float* __restrict__ out) {
    int w = (blockIdx.x * blockDim.x + threadIdx.x) >> 5;
    int lane = threadIdx.x & 31;
    if (w >= NN) return;
    float a0 = 0.f, a1 = 0.f;
    const int c = 2 * lane;                   // lane owns cols c, c+1
    const bool act = c < GP;                  // lanes 0..21
    int beg = g_off[w], end = beg + g_deg[w];
    if (act) {
        int e = beg;
        for (; e + 4 <= end; e += 4) {
            int s0 = g_src[e], s1 = g_src[e + 1], s2 = g_src[e + 2], s3 = g_src[e + 3];
            uint32_t u0 = *(const uint32_t*)(g_g2 + (size_t)s0 * GP + c);
            uint32_t u1 = *(const uint32_t*)(g_g2 + (size_t)s1 * GP + c);
            uint32_t u2 = *(const uint32_t*)(g_g2 + (size_t)s2 * GP + c);
            uint32_t u3 = *(const uint32_t*)(g_g2 + (size_t)s3 * GP + c);
            float2 v0 = __half22float2(*reinterpret_cast<__half2*>(&u0));
            float2 v1 = __half22float2(*reinterpret_cast<__half2*>(&u1));
            float2 v2 = __half22float2(*reinterpret_cast<__half2*>(&u2));
            float2 v3 = __half22float2(*reinterpret_cast<__half2*>(&u3));
            a0 += v0.x + v1.x + v2.x + v3.x;
            a1 += v0.y + v1.y + v2.y + v3.y;
        }
        for (; e < end; e++) {
            uint32_t u = *(const uint32_t*)(g_g2 + (size_t)g_src[e] * GP + c);
            float2 v = __half22float2(*reinterpret_cast<__half2*>(&u));
            a0 += v.x; a1 += v.y;
        }
        uint32_t u = *(const uint32_t*)(g_g2 + (size_t)w * GP + c);
        float2 v = __half22float2(*reinterpret_cast<__half2*>(&u));
        a0 += v.x; a1 += v.y;
    }

    float dd = g_dinv[w];
    float v0 = (c < NC)     ? (dd * a0 + b2[c])     : -INFINITY;
    float v1 = (c + 1 < NC) ? (dd * a1 + b2[c + 1]) : -INFINITY;

    float m = fmaxf(v0, v1);
#pragma unroll
    for (int o = 16; o; o >>= 1) m = fmaxf(m, __shfl_xor_sync(0xffffffffu, m, o));
    float s = ((c < NC) ? expf(v0 - m) : 0.f) + ((c + 1 < NC) ? expf(v1 - m) : 0.f);
#pragma unroll
    for (int o = 16; o; o >>= 1) s += __shfl_xor_sync(0xffffffffu, s, o);
    float ls = logf(s) + m;

    if (c < NC)     out[(size_t)w * NC + c]     = v0 - ls;
    if (c + 1 < NC) out[(size_t)w * NC + c + 1] = v1 - ls;
}

// ---------------- launch -----------------------------------------------------------
extern "C" void kernel_launch(void* const* d_in, const int* in_sizes, int n_in,
                              void* d_out, int out_size) {
    const float* x  = (const float*)d_in[0];
    const void*  e  = d_in[1];
    const float* W1 = (const float*)d_in[2];
    const float* b1 = (const float*)d_in[3];
    const float* W2 = (const float*)d_in[4];
    const float* b2 = (const float*)d_in[5];
    float* out = (float*)d_out;

    cudaFuncSetAttribute(k_gemm1_mma, cudaFuncAttributeMaxDynamicSharedMemorySize, SMEM_G1);
    cudaFuncSetAttribute(k_gemm2_mma, cudaFuncAttributeMaxDynamicSharedMemorySize, SMEM_G2);

    cudaStream_t s;
    cudaEvent_t evFork, evJoin;
    cudaStreamCreateWithFlags(&s, cudaStreamNonBlocking);
    cudaEventCreateWithFlags(&evFork, cudaEventDisableTiming);
    cudaEventCreateWithFlags(&evJoin, cudaEventDisableTiming);

    cudaEventRecord(evFork, 0);
    cudaStreamWaitEvent(s, evFork, 0);

    // GEMM branch (side stream)
    k_w1split<<<(128 * 608 + 255) / 256, 256, 0, s>>>(W1);
    k_gemm1_mma<<<(NN + 127) / 128, 256, SMEM_G1, s>>>(x);
    cudaEventRecord(evJoin, s);

    // prep branch (main/capture stream)
    k_init<<<(NN + 255) / 256, 256>>>();
    k_detect<<<1, 256>>>((const unsigned*)e);
    k_deg<<<(NE + 255) / 256, 256>>>(e);
    k_scan1<<<(NN + 255) / 256, 256>>>();
    k_scan2<<<1, 512>>>();
    k_scan3<<<(NN + 255) / 256, 256>>>();
    k_scatter<<<(NE + 255) / 256, 256>>>(e);
    k_w2split<<<(64 * 128 + 255) / 256, 256>>>(W2);

    cudaStreamWaitEvent(0, evJoin, 0);

    k_agg1<<<(NN * 32 + 255) / 256, 256>>>(b1);
    k_gemm2_mma<<<(NN + 127) / 128, 256, SMEM_G2>>>();
    k_agg2<<<(NN * 32 + 255) / 256, 256>>>(b2, out);
}